// round 12
// baseline (speedup 1.0000x reference)
#include <cuda_runtime.h>

// y[o*16+k, n_out, m] = sum_{i<64, j<3} xs[i][m+j] * W[i, k, j]
// xs: W-rolled + zero-padded input row slab, row stride 60 floats.
//     xs[i][0] = xs[i][57..59] = 0;  xs[i][u] = x[c, n_src, w] with
//     u = w+2 (wrap to 1 when > 56)  -> patches[c,n_src,j,m] == xs[i][m+j].
// n_out = (n_src + 1) % 56 (output H-roll folded into the store).
//
// 1024 threads = 8 slices x 128. slice covers i in [slice*8, slice*8+8).
// Within a slice: k = t&15, g = t>>4; g<7 computes m = g*8 .. g*8+7.
// Each thread PRELOADS its 24 weights (8 i x 3 j, fixed k) into registers
// from a transposed smem copy Wt[k][i][j] (stride 196 floats), so the
// mainloop has only 3 x-loads + 24 FMA per i.
// Slices 1..7 spill partials; slice 0 reduces + stores (2x float4).

static constexpr int WT_STRIDE = 196;                    // floats per k row
static constexpr int XS_OFF = 0;                         // 64*60
static constexpr int WT_OFF = XS_OFF + 64 * 60;          // 3840
static constexpr int PS_OFF = WT_OFF + 16 * WT_STRIDE;   // 3840+3136 = 6976
static constexpr int SMEM_FLOATS = PS_OFF + 7 * 112 * 8; // 6976+6272 = 13248
static constexpr int SMEM_BYTES  = SMEM_FLOATS * 4;      // 52992

__global__ __launch_bounds__(1024, 1)
void shiftconv_kernel(const float* __restrict__ x,
                      const float* __restrict__ Wg,
                      float* __restrict__ y)
{
    extern __shared__ float sm[];
    float* xs = sm + XS_OFF;
    float* Wt = sm + WT_OFF;
    float* ps = sm + PS_OFF;

    const int n_src = blockIdx.x;            // 0..55
    const int o     = blockIdx.y;            // 0..1
    const int tid   = threadIdx.x;           // 0..1023

    // ---- stage W transposed: Wt[k*196 + i*3 + j] = Wg[i*48 + k*3 + j] ----
    #pragma unroll
    for (int idx = tid; idx < 64 * 48; idx += 1024) {
        const int i = idx / 48;
        const int r = idx - i * 48;          // k*3 + j
        const int k = r / 3;
        const int j = r - k * 3;
        Wt[k * WT_STRIDE + i * 3 + j] = Wg[idx];
    }

    // ---- zero xs pad columns (u = 0, 57, 58, 59) ----
    if (tid < 64) {
        xs[tid * 60 + 0]  = 0.0f;
        xs[tid * 60 + 57] = 0.0f;
        xs[tid * 60 + 58] = 0.0f;
        xs[tid * 60 + 59] = 0.0f;
    }

    // ---- stage x: one float4 per thread (64 rows x 14 quads); W-roll folded ----
    const float* xbase = x + (o * 64) * 3136 + n_src * 56;
    if (tid < 896) {
        const int i = tid / 14;
        const int q = tid - i * 14;
        const int w = q * 4;
        const float4 v = *(const float4*)(xbase + i * 3136 + w);
        float* row = &xs[i * 60];
        int u0 = w + 2; if (u0 > 56) u0 -= 56;
        int u1 = w + 3; if (u1 > 56) u1 -= 56;
        int u2 = w + 4; if (u2 > 56) u2 -= 56;
        int u3 = w + 5; if (u3 > 56) u3 -= 56;
        row[u0] = v.x; row[u1] = v.y; row[u2] = v.z; row[u3] = v.w;
    }
    __syncthreads();

    const int slice = tid >> 7;              // 0..7
    const int t128  = tid & 127;
    const int k     = t128 & 15;
    const int g     = t128 >> 4;             // 0..7 (7 == idle in compute)
    const int m0    = g * 8;
    const int i0    = slice * 8;
    const bool live = (g < 7);

    float acc[8];
    #pragma unroll
    for (int t = 0; t < 8; t++) acc[t] = 0.0f;

    if (live) {
        // ---- preload this thread's 24 weights (aligned: k*196 + slice*24 ≡ 0 mod 4) ----
        float wv[24];
        const float* wp = Wt + k * WT_STRIDE + i0 * 3;
        #pragma unroll
        for (int t = 0; t < 6; t++) {
            const float4 v = *(const float4*)(wp + t * 4);
            wv[t * 4 + 0] = v.x; wv[t * 4 + 1] = v.y;
            wv[t * 4 + 2] = v.z; wv[t * 4 + 3] = v.w;
        }

        #pragma unroll
        for (int ii = 0; ii < 8; ii++) {
            const float w0 = wv[ii * 3 + 0];
            const float w1 = wv[ii * 3 + 1];
            const float w2 = wv[ii * 3 + 2];

            const float* xr = xs + (i0 + ii) * 60 + m0;   // 16B aligned
            const float4 a = *(const float4*)(xr);
            const float4 b = *(const float4*)(xr + 4);
            const float2 c = *(const float2*)(xr + 8);
            const float xv[10] = {a.x, a.y, a.z, a.w, b.x, b.y, b.z, b.w, c.x, c.y};

            #pragma unroll
            for (int t = 0; t < 8; t++)
                acc[t] = fmaf(w2, xv[t + 2],
                         fmaf(w1, xv[t + 1],
                         fmaf(w0, xv[t], acc[t])));
        }
    }

    // ---- cross-slice reduction ----
    const int a_idx = g * 16 + k;            // 0..111 for live threads
    if (slice > 0 && live) {
        float* p = &ps[((slice - 1) * 112 + a_idx) * 8];
        *(float4*)(p)     = make_float4(acc[0], acc[1], acc[2], acc[3]);
        *(float4*)(p + 4) = make_float4(acc[4], acc[5], acc[6], acc[7]);
    }
    __syncthreads();

    if (slice == 0 && live) {
        #pragma unroll
        for (int s = 0; s < 7; s++) {
            const float* p = &ps[(s * 112 + a_idx) * 8];
            const float4 u = *(const float4*)(p);
            const float4 v = *(const float4*)(p + 4);
            acc[0] += u.x; acc[1] += u.y; acc[2] += u.z; acc[3] += u.w;
            acc[4] += v.x; acc[5] += v.y; acc[6] += v.z; acc[7] += v.w;
        }

        int n_out = n_src + 1;
        if (n_out == 56) n_out = 0;
        float* ybase = y + (o * 16 + k) * 3136 + n_out * 56 + m0;
        *(float4*)(ybase)     = make_float4(acc[0], acc[1], acc[2], acc[3]);
        *(float4*)(ybase + 4) = make_float4(acc[4], acc[5], acc[6], acc[7]);
    }
}

extern "C" void kernel_launch(void* const* d_in, const int* in_sizes, int n_in,
                              void* d_out, int out_size)
{
    const float* x  = (const float*)d_in[0];   // (1,128,56,56) = 401408
    const float* Wg = (const float*)d_in[1];   // (64,16,3)     = 3072
    float* y = (float*)d_out;                  // (1,32,56,56)  = 100352

    static bool attr_set = false;
    if (!attr_set) {
        cudaFuncSetAttribute(shiftconv_kernel,
                             cudaFuncAttributeMaxDynamicSharedMemorySize,
                             SMEM_BYTES);
        attr_set = true;
    }

    dim3 grid(56, 2);
    shiftconv_kernel<<<grid, 1024, SMEM_BYTES>>>(x, Wg, y);
}

// round 13
// speedup vs baseline: 1.2143x; 1.2143x over previous
#include <cuda_runtime.h>

// y[o*16+k, n_out, m] = sum_{i<64, j<3} xs[i][m+j] * W[i, k, j]
// xs: W-rolled + zero-padded input row slab, row stride 60 floats.
//     xs[i][0] = xs[i][57..59] = 0;  xs[i][u] = x[c, n_src, w] with
//     u = w+2 (wrap to 1 when > 56)  -> patches[c,n_src,j,m] == xs[i][m+j].
// n_out = (n_src + 1) % 56 (output H-roll folded into the store).
//
// 1024 threads = 8 slices x 128. slice covers i in [slice*8, slice*8+8).
// Within a slice: k = t&15, g = t>>4; g<7 computes m = g*8 .. g*8+7.
// ALL slices spill partials (stride 12 floats: conflict-free, 16B aligned);
// then 224 threads reduce one float4 each across the 8 slices and store.

static constexpr int XS_OFF = 0;                          // 64*60 = 3840
static constexpr int WS_OFF = XS_OFF + 64 * 60;           // 3840
static constexpr int PS_OFF = WS_OFF + 64 * 48;           // 6912
static constexpr int PS_STRIDE = 12;                      // floats per a_idx
static constexpr int PS_SLICE  = 112 * PS_STRIDE;         // 1344 floats/slice
static constexpr int SMEM_FLOATS = PS_OFF + 8 * PS_SLICE; // 6912+10752 = 17664
static constexpr int SMEM_BYTES  = SMEM_FLOATS * 4;       // 70656

__global__ __launch_bounds__(1024, 1)
void shiftconv_kernel(const float* __restrict__ x,
                      const float* __restrict__ Wg,
                      float* __restrict__ y)
{
    extern __shared__ float sm[];
    float* xs = sm + XS_OFF;
    float* Ws = sm + WS_OFF;
    float* ps = sm + PS_OFF;

    const int n_src = blockIdx.x;            // 0..55
    const int o     = blockIdx.y;            // 0..1
    const int tid   = threadIdx.x;           // 0..1023

    // ---- issue the x global load FIRST (latency overlapped with W staging) ----
    const float* xbase = x + (o * 64) * 3136 + n_src * 56;
    const bool xthr = (tid < 896);
    int xi = 0, xw = 0;
    float4 xv4 = make_float4(0.f, 0.f, 0.f, 0.f);
    if (xthr) {
        xi = tid / 14;                       // row i
        const int q = tid - xi * 14;
        xw = q * 4;
        xv4 = *(const float4*)(xbase + xi * 3136 + xw);
    }

    // ---- stage W (same layout as global: Ws[i*48 + k*3 + j]) ----
    #pragma unroll
    for (int idx = tid; idx < 64 * 48; idx += 1024)
        Ws[idx] = Wg[idx];

    // ---- zero xs pad columns using the spare 128 threads ----
    if (tid >= 896) {
        const int r = tid - 896;             // 0..127
        if (r < 64) {
            xs[r * 60 + 0]  = 0.0f;
            xs[r * 60 + 57] = 0.0f;
            xs[r * 60 + 58] = 0.0f;
            xs[r * 60 + 59] = 0.0f;
        }
    }

    // ---- scatter x into xs with the W-dim roll folded in ----
    if (xthr) {
        float* row = &xs[xi * 60];
        int u0 = xw + 2; if (u0 > 56) u0 -= 56;
        int u1 = xw + 3; if (u1 > 56) u1 -= 56;
        int u2 = xw + 4; if (u2 > 56) u2 -= 56;
        int u3 = xw + 5; if (u3 > 56) u3 -= 56;
        row[u0] = xv4.x; row[u1] = xv4.y; row[u2] = xv4.z; row[u3] = xv4.w;
    }
    __syncthreads();

    // ---- compute (R7-proven mainloop: broadcast LDS for x and W) ----
    const int slice = tid >> 7;              // 0..7
    const int t128  = tid & 127;
    const int k     = t128 & 15;
    const int g     = t128 >> 4;             // 0..7 (7 == idle in compute)
    const int m0    = g * 8;
    const int i0    = slice * 8;
    const bool live = (g < 7);

    if (live) {
        float acc[8];
        #pragma unroll
        for (int t = 0; t < 8; t++) acc[t] = 0.0f;

        #pragma unroll
        for (int ii = 0; ii < 8; ii++) {
            const int i = i0 + ii;
            const float* wrow = &Ws[i * 48 + k * 3];
            const float w0 = wrow[0];
            const float w1 = wrow[1];
            const float w2 = wrow[2];

            const float* xr = xs + i * 60 + m0;          // 16B aligned
            const float4 a = *(const float4*)(xr);
            const float4 b = *(const float4*)(xr + 4);
            const float2 c = *(const float2*)(xr + 8);
            const float xv[10] = {a.x, a.y, a.z, a.w, b.x, b.y, b.z, b.w, c.x, c.y};

            #pragma unroll
            for (int t = 0; t < 8; t++)
                acc[t] = fmaf(w2, xv[t + 2],
                         fmaf(w1, xv[t + 1],
                         fmaf(w0, xv[t], acc[t])));
        }

        // spill: ps[slice][a_idx][0..7], a_idx stride 12 floats
        const int a_idx = g * 16 + k;                    // 0..111
        float* p = &ps[slice * PS_SLICE + a_idx * PS_STRIDE];
        *(float4*)(p)     = make_float4(acc[0], acc[1], acc[2], acc[3]);
        *(float4*)(p + 4) = make_float4(acc[4], acc[5], acc[6], acc[7]);
    }
    __syncthreads();

    // ---- parallel reduce: 224 threads, one float4 each across 8 slices ----
    if (tid < 224) {
        const int a_idx = tid >> 1;                      // 0..111
        const int h     = tid & 1;                       // float4 half
        const float* base = &ps[a_idx * PS_STRIDE + h * 4];

        float4 s = *(const float4*)(base);
        #pragma unroll
        for (int sl = 1; sl < 8; sl++) {
            const float4 v = *(const float4*)(base + sl * PS_SLICE);
            s.x += v.x; s.y += v.y; s.z += v.z; s.w += v.w;
        }

        const int kk = a_idx & 15;
        const int gg = a_idx >> 4;
        int n_out = n_src + 1;
        if (n_out == 56) n_out = 0;
        float* yp = y + (o * 16 + kk) * 3136 + n_out * 56 + gg * 8 + h * 4;
        *(float4*)yp = s;
    }
}

extern "C" void kernel_launch(void* const* d_in, const int* in_sizes, int n_in,
                              void* d_out, int out_size)
{
    const float* x  = (const float*)d_in[0];   // (1,128,56,56) = 401408
    const float* Wg = (const float*)d_in[1];   // (64,16,3)     = 3072
    float* y = (float*)d_out;                  // (1,32,56,56)  = 100352

    static bool attr_set = false;
    if (!attr_set) {
        cudaFuncSetAttribute(shiftconv_kernel,
                             cudaFuncAttributeMaxDynamicSharedMemorySize,
                             SMEM_BYTES);
        attr_set = true;
    }

    dim3 grid(56, 2);
    shiftconv_kernel<<<grid, 1024, SMEM_BYTES>>>(x, Wg, y);
}